// round 7
// baseline (speedup 1.0000x reference)
#include <cuda_runtime.h>
#include <cuda_bf16.h>
#include <cstdint>

#define NA 100000
#define NB 100000
#define IN_DIM 256
#define OUT_DIM 256
#define NE 320000
#define LN_EPS 1e-5f

#define NBIN (2 * NA)            // 200000 (p, dst) bins
#define SCAN_B 512
#define NBLK ((NBIN + SCAN_B - 1) / SCAN_B)   // 391

#define SLAB_TILES 196
#define SLAB_ROWS (SLAB_TILES * 128)          // 25088
#define NSLAB 4

// ---------------- scratch (device globals; no allocation allowed) -----------
__device__ float g_agg[(size_t)2 * NA * 256];        // per-path mean+bias
__device__ float g_cnt[NBIN];
__device__ __nv_bfloat16 g_Shi[(size_t)NBIN * 256];  // aggregated sums, bf16 hi
__device__ __nv_bfloat16 g_Slo[(size_t)NBIN * 256];  // bf16 lo residual
__device__ __nv_bfloat16 g_Wt_hi[512 * 256];         // Wcat^T [n][k]
__device__ __nv_bfloat16 g_Wt_lo[512 * 256];
__device__ int g_hist[NBIN];
__device__ int g_rowptr[NBIN];
__device__ int g_cursor[NBIN];
__device__ int g_elist[2 * NE];
__device__ int g_blocksums[SCAN_B];
__device__ int g_blockoff[SCAN_B];

// ---------------- helpers ----------------------------------------------------
__device__ __forceinline__ uint32_t smem_u32(const void* p) {
    uint32_t a;
    asm("{ .reg .u64 t; cvta.to.shared.u64 t, %1; cvt.u32.u64 %0, t; }" : "=r"(a) : "l"(p));
    return a;
}
__device__ __forceinline__ void ldsm_x4(uint32_t& r0, uint32_t& r1, uint32_t& r2,
                                        uint32_t& r3, uint32_t addr) {
    asm volatile("ldmatrix.sync.aligned.m8n8.x4.shared.b16 {%0,%1,%2,%3}, [%4];"
                 : "=r"(r0), "=r"(r1), "=r"(r2), "=r"(r3) : "r"(addr));
}
__device__ __forceinline__ void mma_bf16(float* c, const uint32_t* a, const uint32_t* b) {
    asm volatile("mma.sync.aligned.m16n8k16.row.col.f32.bf16.bf16.f32 "
                 "{%0,%1,%2,%3}, {%4,%5,%6,%7}, {%8,%9}, {%0,%1,%2,%3};"
                 : "+f"(c[0]), "+f"(c[1]), "+f"(c[2]), "+f"(c[3])
                 : "r"(a[0]), "r"(a[1]), "r"(a[2]), "r"(a[3]), "r"(b[0]), "r"(b[1]));
}
#define CP_ASYNC16(sm, gp) \
    asm volatile("cp.async.cg.shared.global [%0], [%1], 16;" \
                 :: "r"(sm), "l"(gp) : "memory")
#define CP_ASYNC16Z(sm, gp, sz) \
    asm volatile("cp.async.cg.shared.global [%0], [%1], 16, %2;" \
                 :: "r"(sm), "l"(gp), "r"(sz) : "memory")
#define CP_COMMIT() asm volatile("cp.async.commit_group;" ::: "memory")
#define CP_WAIT0()  asm volatile("cp.async.wait_group 0;" ::: "memory")
#define CP_WAIT1()  asm volatile("cp.async.wait_group 1;" ::: "memory")
#define CP_WAIT2()  asm volatile("cp.async.wait_group 2;" ::: "memory")

// ---------------- zero: out_B + hist -----------------------------------------
__global__ __launch_bounds__(256) void zero_kernel(float* __restrict__ outB) {
    size_t i = (size_t)blockIdx.x * 256 + threadIdx.x;
    const size_t n4_outB = (size_t)NB * OUT_DIM / 4;
    const size_t n4_hist = NBIN / 4;
    if (i < n4_outB) {
        reinterpret_cast<float4*>(outB)[i] = make_float4(0.f, 0.f, 0.f, 0.f);
    } else if (i < n4_outB + n4_hist) {
        reinterpret_cast<int4*>(g_hist)[i - n4_outB] = make_int4(0, 0, 0, 0);
    }
}

// ---------------- W split/transpose prep ------------------------------------
__global__ __launch_bounds__(256) void splitW_kernel(const float* __restrict__ W0,
                                                     const float* __restrict__ W1) {
    int n = blockIdx.x;
    int k = threadIdx.x;
    float w = (n < 256) ? W0[k * 256 + n] : W1[k * 256 + (n - 256)];
    __nv_bfloat16 h = __float2bfloat16_rn(w);
    float r = w - __bfloat162float(h);
    g_Wt_hi[n * 256 + k] = h;
    g_Wt_lo[n * 256 + k] = __float2bfloat16_rn(r);
}

// ---------------- CSR build --------------------------------------------------
__global__ __launch_bounds__(256) void hist_kernel(
    const int* __restrict__ ei0, const int* __restrict__ ei1)
{
    int i = blockIdx.x * 256 + threadIdx.x;
    if (i >= 2 * NE) return;
    int p = (i >= NE) ? 1 : 0;
    int e = i - p * NE;
    const int* __restrict__ ei = p ? ei1 : ei0;
    int dst = ei[e + NE];
    atomicAdd(&g_hist[p * NA + dst], 1);
}

__global__ __launch_bounds__(SCAN_B) void scanA_kernel() {
    __shared__ int sh[SCAN_B];
    int i = blockIdx.x * SCAN_B + threadIdx.x;
    sh[threadIdx.x] = (i < NBIN) ? g_hist[i] : 0;
    __syncthreads();
    for (int d = SCAN_B / 2; d > 0; d >>= 1) {
        if (threadIdx.x < d) sh[threadIdx.x] += sh[threadIdx.x + d];
        __syncthreads();
    }
    if (threadIdx.x == 0) g_blocksums[blockIdx.x] = sh[0];
}

__global__ __launch_bounds__(SCAN_B) void scanB_kernel() {
    __shared__ int sh[SCAN_B];
    int tid = threadIdx.x;
    int v = (tid < NBLK) ? g_blocksums[tid] : 0;
    sh[tid] = v;
    __syncthreads();
    for (int d = 1; d < SCAN_B; d <<= 1) {
        int t = (tid >= d) ? sh[tid - d] : 0;
        __syncthreads();
        sh[tid] += t;
        __syncthreads();
    }
    if (tid < NBLK) g_blockoff[tid] = sh[tid] - v;   // exclusive
}

__global__ __launch_bounds__(SCAN_B) void scanC_kernel() {
    __shared__ int sh[SCAN_B];
    int tid = threadIdx.x;
    int i = blockIdx.x * SCAN_B + tid;
    int v = (i < NBIN) ? g_hist[i] : 0;
    sh[tid] = v;
    __syncthreads();
    for (int d = 1; d < SCAN_B; d <<= 1) {
        int t = (tid >= d) ? sh[tid - d] : 0;
        __syncthreads();
        sh[tid] += t;
        __syncthreads();
    }
    if (i < NBIN) {
        int excl = sh[tid] - v + g_blockoff[blockIdx.x];
        g_rowptr[i] = excl;
        g_cursor[i] = excl;
        g_cnt[i] = (float)v;
    }
}

__global__ __launch_bounds__(256) void fill_kernel(
    const int* __restrict__ ei0, const int* __restrict__ ei1)
{
    int i = blockIdx.x * 256 + threadIdx.x;
    if (i >= 2 * NE) return;
    int p = (i >= NE) ? 1 : 0;
    int e = i - p * NE;
    const int* __restrict__ ei = p ? ei1 : ei0;
    int src = ei[e];
    int dst = ei[e + NE];
    int pos = atomicAdd(&g_cursor[p * NA + dst], 1);
    g_elist[pos] = src;
}

// ---------------- aggregate (slab): warp per (p, dst) ------------------------
__global__ __launch_bounds__(256) void agg_kernel(const float* __restrict__ xB,
                                                  int row0, int nrows) {
    int w = (blockIdx.x * 256 + threadIdx.x) >> 5;
    int lane = threadIdx.x & 31;
    if (w >= 2 * nrows) return;
    int p = (w >= nrows) ? 1 : 0;
    int bin = p * NA + row0 + (w - p * nrows);
    int start = g_rowptr[bin];
    int deg = g_hist[bin];

    float a[8] = {0.f, 0.f, 0.f, 0.f, 0.f, 0.f, 0.f, 0.f};

    int j = 0;
    for (; j + 4 <= deg; j += 4) {
        int s0 = __ldg(&g_elist[start + j]);
        int s1 = __ldg(&g_elist[start + j + 1]);
        int s2 = __ldg(&g_elist[start + j + 2]);
        int s3 = __ldg(&g_elist[start + j + 3]);
        const float4* r0 = reinterpret_cast<const float4*>(xB + (size_t)s0 * 256) + lane * 2;
        const float4* r1 = reinterpret_cast<const float4*>(xB + (size_t)s1 * 256) + lane * 2;
        const float4* r2 = reinterpret_cast<const float4*>(xB + (size_t)s2 * 256) + lane * 2;
        const float4* r3 = reinterpret_cast<const float4*>(xB + (size_t)s3 * 256) + lane * 2;
        float4 v0a = r0[0], v0b = r0[1];
        float4 v1a = r1[0], v1b = r1[1];
        float4 v2a = r2[0], v2b = r2[1];
        float4 v3a = r3[0], v3b = r3[1];
        a[0] += v0a.x + v1a.x + v2a.x + v3a.x;
        a[1] += v0a.y + v1a.y + v2a.y + v3a.y;
        a[2] += v0a.z + v1a.z + v2a.z + v3a.z;
        a[3] += v0a.w + v1a.w + v2a.w + v3a.w;
        a[4] += v0b.x + v1b.x + v2b.x + v3b.x;
        a[5] += v0b.y + v1b.y + v2b.y + v3b.y;
        a[6] += v0b.z + v1b.z + v2b.z + v3b.z;
        a[7] += v0b.w + v1b.w + v2b.w + v3b.w;
    }
    for (; j < deg; j++) {
        int src = __ldg(&g_elist[start + j]);
        const float4* r4 = reinterpret_cast<const float4*>(xB + (size_t)src * 256) + lane * 2;
        float4 v0 = r4[0], v1 = r4[1];
        a[0] += v0.x; a[1] += v0.y; a[2] += v0.z; a[3] += v0.w;
        a[4] += v1.x; a[5] += v1.y; a[6] += v1.z; a[7] += v1.w;
    }

    uint4 hv, lv;
    {
        __nv_bfloat162 h0 = __floats2bfloat162_rn(a[0], a[1]);
        __nv_bfloat162 h1 = __floats2bfloat162_rn(a[2], a[3]);
        __nv_bfloat162 h2 = __floats2bfloat162_rn(a[4], a[5]);
        __nv_bfloat162 h3 = __floats2bfloat162_rn(a[6], a[7]);
        __nv_bfloat162 l0 = __floats2bfloat162_rn(a[0] - __bfloat162float(h0.x),
                                                  a[1] - __bfloat162float(h0.y));
        __nv_bfloat162 l1 = __floats2bfloat162_rn(a[2] - __bfloat162float(h1.x),
                                                  a[3] - __bfloat162float(h1.y));
        __nv_bfloat162 l2 = __floats2bfloat162_rn(a[4] - __bfloat162float(h2.x),
                                                  a[5] - __bfloat162float(h2.y));
        __nv_bfloat162 l3 = __floats2bfloat162_rn(a[6] - __bfloat162float(h3.x),
                                                  a[7] - __bfloat162float(h3.y));
        hv.x = *reinterpret_cast<uint32_t*>(&h0); hv.y = *reinterpret_cast<uint32_t*>(&h1);
        hv.z = *reinterpret_cast<uint32_t*>(&h2); hv.w = *reinterpret_cast<uint32_t*>(&h3);
        lv.x = *reinterpret_cast<uint32_t*>(&l0); lv.y = *reinterpret_cast<uint32_t*>(&l1);
        lv.z = *reinterpret_cast<uint32_t*>(&l2); lv.w = *reinterpret_cast<uint32_t*>(&l3);
    }
    *reinterpret_cast<uint4*>(g_Shi + (size_t)bin * 256 + lane * 8) = hv;
    *reinterpret_cast<uint4*>(g_Slo + (size_t)bin * 256 + lane * 8) = lv;
}

// ---------------- HMMA GEMM (slab): agg = (S @ W)/cnt + b -------------------
#define GBUF 32768
#define GSM_TOTAL (3 * GBUF)

__device__ __forceinline__ void gemm_issue(
    uint32_t sb, int tid, int m0,
    const __nv_bfloat16* __restrict__ Ahi, const __nv_bfloat16* __restrict__ Alo,
    const __nv_bfloat16* __restrict__ Bhi, const __nv_bfloat16* __restrict__ Blo,
    int kc)
{
#pragma unroll
    for (int l = 0; l < 4; l++) {
        int ulin = l * 256 + tid;
        int r = ulin >> 3, u = ulin & 7;
        int grow = m0 + r;
        int ok = (grow < NA) ? 16 : 0;
        int grc = (grow < NA) ? grow : (NA - 1);
        uint32_t dst = sb + (uint32_t)(r * 128 + ((u ^ (r & 7)) << 4));
        const __nv_bfloat16* src = (u < 4)
            ? (Ahi + (size_t)grc * 256 + kc * 32 + (u & 3) * 8)
            : (Alo + (size_t)grc * 256 + kc * 32 + (u & 3) * 8);
        CP_ASYNC16Z(dst, src, ok);
    }
#pragma unroll
    for (int l = 0; l < 4; l++) {
        int ulin = l * 256 + tid;
        int n = ulin >> 3, u = ulin & 7;
        uint32_t dst = sb + 16384u + (uint32_t)(n * 128 + ((u ^ (n & 7)) << 4));
        const __nv_bfloat16* src = (u < 4)
            ? (Bhi + (size_t)n * 256 + kc * 32 + (u & 3) * 8)
            : (Blo + (size_t)n * 256 + kc * 32 + (u & 3) * 8);
        CP_ASYNC16(dst, src);
    }
    CP_COMMIT();
}

__global__ __launch_bounds__(256, 2) void gemm_mma_kernel(
    const float* __restrict__ b0, const float* __restrict__ b1, int mbase)
{
    extern __shared__ char smem[];
    const uint32_t sbase = smem_u32(smem);
    const int tid = threadIdx.x, lane = tid & 31, wid = tid >> 5;
    const int wm = wid & 3;
    const int wn = wid >> 2;
    const int p = blockIdx.x >> 1, h = blockIdx.x & 1;
    const int m0 = mbase + blockIdx.y * 128;

    const __nv_bfloat16* __restrict__ Ahi = g_Shi + (size_t)p * NA * 256;
    const __nv_bfloat16* __restrict__ Alo = g_Slo + (size_t)p * NA * 256;
    const __nv_bfloat16* __restrict__ Bhi = g_Wt_hi + (size_t)(p * 256 + h * 128) * 256;
    const __nv_bfloat16* __restrict__ Blo = g_Wt_lo + (size_t)(p * 256 + h * 128) * 256;

    float c[2][8][4];
#pragma unroll
    for (int mt = 0; mt < 2; mt++)
#pragma unroll
        for (int n8 = 0; n8 < 8; n8++)
#pragma unroll
            for (int q = 0; q < 4; q++) c[mt][n8][q] = 0.f;

    const int am = lane & 15;
    const int aoff = lane >> 4;
    const int asw = am & 7;
    const int bn = (lane & 7) | ((lane & 16) >> 1);
    const int boff = (lane >> 3) & 1;
    const int bsw = bn & 7;

    gemm_issue(sbase, tid, m0, Ahi, Alo, Bhi, Blo, 0);
    gemm_issue(sbase + GBUF, tid, m0, Ahi, Alo, Bhi, Blo, 1);

    for (int kc = 0; kc < 8; kc++) {
        if (kc + 2 < 8) {
            gemm_issue(sbase + ((kc + 2) % 3) * GBUF, tid, m0, Ahi, Alo, Bhi, Blo, kc + 2);
            CP_WAIT2();
        } else if (kc + 1 < 8) {
            CP_WAIT1();
        } else {
            CP_WAIT0();
        }
        __syncthreads();
        const uint32_t sb = sbase + (kc % 3) * GBUF;

#pragma unroll
        for (int s = 0; s < 2; s++) {
            const int uhi = (s << 1) | aoff;
            uint32_t ah[2][4], al[2][4];
#pragma unroll
            for (int mt = 0; mt < 2; mt++) {
                int arow = wm * 32 + mt * 16 + am;
                uint32_t rb = sb + (uint32_t)(arow * 128);
                ldsm_x4(ah[mt][0], ah[mt][1], ah[mt][2], ah[mt][3],
                        rb + ((uhi ^ asw) << 4));
                ldsm_x4(al[mt][0], al[mt][1], al[mt][2], al[mt][3],
                        rb + (((4 | uhi) ^ asw) << 4));
            }
            const int vhi = (s << 1) | boff;
#pragma unroll
            for (int g = 0; g < 4; g++) {
                int brow = wn * 64 + g * 16 + bn;
                uint32_t rb = sb + 16384u + (uint32_t)(brow * 128);
                uint32_t bh[4], bl[4];
                ldsm_x4(bh[0], bh[1], bh[2], bh[3], rb + ((vhi ^ bsw) << 4));
                ldsm_x4(bl[0], bl[1], bl[2], bl[3], rb + (((4 | vhi) ^ bsw) << 4));
#pragma unroll
                for (int mt = 0; mt < 2; mt++) {
                    mma_bf16(c[mt][2 * g],     ah[mt], &bh[0]);
                    mma_bf16(c[mt][2 * g],     ah[mt], &bl[0]);
                    mma_bf16(c[mt][2 * g],     al[mt], &bh[0]);
                    mma_bf16(c[mt][2 * g + 1], ah[mt], &bh[2]);
                    mma_bf16(c[mt][2 * g + 1], ah[mt], &bl[2]);
                    mma_bf16(c[mt][2 * g + 1], al[mt], &bh[2]);
                }
            }
        }
        __syncthreads();
    }

    // ---- epilogue: mean + bias -> g_agg ------------------------------------
    const float* __restrict__ bias = p ? b1 : b0;
    float* __restrict__ dst = g_agg + (size_t)p * NA * 256;
#pragma unroll
    for (int mt = 0; mt < 2; mt++) {
#pragma unroll
        for (int rr = 0; rr < 2; rr++) {
            int row = m0 + wm * 32 + mt * 16 + rr * 8 + (lane >> 2);
            if (row >= NA) continue;
            float cv = g_cnt[p * NA + row];
            float inv = cv > 0.f ? 1.f / cv : 0.f;
            float bf = cv > 0.f ? 1.f : 0.f;
            float* orow = dst + (size_t)row * 256;
#pragma unroll
            for (int n8 = 0; n8 < 8; n8++) {
                int col = h * 128 + wn * 64 + n8 * 8 + (lane & 3) * 2;
                float2 o;
                o.x = c[mt][n8][rr * 2 + 0] * inv + bias[col] * bf;
                o.y = c[mt][n8][rr * 2 + 1] * inv + bias[col + 1] * bf;
                *reinterpret_cast<float2*>(orow + col) = o;
            }
        }
    }
}

// ---------------- finalize (slab): one warp per destination row --------------
__global__ __launch_bounds__(256) void finalize_kernel(
    const float* __restrict__ sem, const float* __restrict__ gamma,
    const float* __restrict__ beta, float* __restrict__ outA,
    int row0, int nrows)
{
    int wi = (blockIdx.x * 256 + threadIdx.x) >> 5;
    int lane = threadIdx.x & 31;
    if (wi >= nrows) return;
    int n = row0 + wi;
    int base = lane * 8;

    const float* a0p = g_agg + (size_t)n * 256;
    const float* a1p = g_agg + ((size_t)NA + n) * 256;

    float a0[8], a1[8], sv[8];
    *reinterpret_cast<float4*>(&a0[0]) = *reinterpret_cast<const float4*>(a0p + base);
    *reinterpret_cast<float4*>(&a0[4]) = *reinterpret_cast<const float4*>(a0p + base + 4);
    *reinterpret_cast<float4*>(&a1[0]) = *reinterpret_cast<const float4*>(a1p + base);
    *reinterpret_cast<float4*>(&a1[4]) = *reinterpret_cast<const float4*>(a1p + base + 4);
    *reinterpret_cast<float4*>(&sv[0]) = *reinterpret_cast<const float4*>(sem + base);
    *reinterpret_cast<float4*>(&sv[4]) = *reinterpret_cast<const float4*>(sem + base + 4);

    float s0 = 0.f, s1 = 0.f;
#pragma unroll
    for (int i = 0; i < 8; i++) {
        s0 += tanhf(a0[i]) * sv[i];
        s1 += tanhf(a1[i]) * sv[i];
    }
#pragma unroll
    for (int o = 16; o > 0; o >>= 1) {
        s0 += __shfl_xor_sync(0xffffffffu, s0, o);
        s1 += __shfl_xor_sync(0xffffffffu, s1, o);
    }
    float m = fmaxf(s0, s1);
    float e0 = __expf(s0 - m), e1 = __expf(s1 - m);
    float w0 = e0 / (e0 + e1);
    float w1 = 1.0f - w0;

    float f[8];
    float sum = 0.f, sq = 0.f;
#pragma unroll
    for (int i = 0; i < 8; i++) {
        f[i] = fmaxf(w0 * a0[i] + w1 * a1[i], 0.f);
        sum += f[i];
        sq  += f[i] * f[i];
    }
#pragma unroll
    for (int o = 16; o > 0; o >>= 1) {
        sum += __shfl_xor_sync(0xffffffffu, sum, o);
        sq  += __shfl_xor_sync(0xffffffffu, sq, o);
    }
    float mu  = sum * (1.0f / 256.0f);
    float var = sq * (1.0f / 256.0f) - mu * mu;
    float rstd = rsqrtf(var + LN_EPS);

    float gm[8], bt[8];
    *reinterpret_cast<float4*>(&gm[0]) = *reinterpret_cast<const float4*>(gamma + base);
    *reinterpret_cast<float4*>(&gm[4]) = *reinterpret_cast<const float4*>(gamma + base + 4);
    *reinterpret_cast<float4*>(&bt[0]) = *reinterpret_cast<const float4*>(beta + base);
    *reinterpret_cast<float4*>(&bt[4]) = *reinterpret_cast<const float4*>(beta + base + 4);

    float o8[8];
#pragma unroll
    for (int i = 0; i < 8; i++)
        o8[i] = (f[i] - mu) * rstd * gm[i] + bt[i];

    float* op = outA + (size_t)n * 256 + base;
    *reinterpret_cast<float4*>(op)     = *reinterpret_cast<float4*>(&o8[0]);
    *reinterpret_cast<float4*>(op + 4) = *reinterpret_cast<float4*>(&o8[4]);
}

// ---------------- launch ----------------------------------------------------
extern "C" void kernel_launch(void* const* d_in, const int* in_sizes, int n_in,
                              void* d_out, int out_size)
{
    const float* x_B  = (const float*)d_in[1];
    const int*   ei0  = (const int*)d_in[2];
    const int*   ei1  = (const int*)d_in[3];
    const float* W0   = (const float*)d_in[4];
    const float* b0   = (const float*)d_in[5];
    const float* W1   = (const float*)d_in[6];
    const float* b1   = (const float*)d_in[7];
    const float* sem  = (const float*)d_in[8];
    const float* gam  = (const float*)d_in[9];
    const float* bet  = (const float*)d_in[10];

    float* outA = (float*)d_out;
    float* outB = outA + (size_t)NA * OUT_DIM;

    cudaFuncSetAttribute(gemm_mma_kernel,
                         cudaFuncAttributeMaxDynamicSharedMemorySize, GSM_TOTAL);

    // 1) zero out_B + hist
    {
        size_t total = (size_t)NB * OUT_DIM / 4 + NBIN / 4;
        zero_kernel<<<(int)((total + 255) / 256), 256>>>(outB);
    }
    // 2) split + transpose W -> bf16 hi/lo
    splitW_kernel<<<512, 256>>>(W0, W1);
    // 3) CSR build: histogram -> scan -> fill
    hist_kernel<<<(2 * NE + 255) / 256, 256>>>(ei0, ei1);
    scanA_kernel<<<NBLK, SCAN_B>>>();
    scanB_kernel<<<1, SCAN_B>>>();
    scanC_kernel<<<NBLK, SCAN_B>>>();
    fill_kernel<<<(2 * NE + 255) / 256, 256>>>(ei0, ei1);

    // 4) slab-interleaved pipeline: agg(s) -> gemm(s) -> finalize(s)
    for (int s = 0; s < NSLAB; s++) {
        int row0 = s * SLAB_ROWS;
        int nrows = (NA - row0 < SLAB_ROWS) ? (NA - row0) : SLAB_ROWS;
        int mtiles = (nrows + 127) / 128;

        agg_kernel<<<(2 * nrows * 32 + 255) / 256, 256>>>(x_B, row0, nrows);

        dim3 grid(4, mtiles);
        gemm_mma_kernel<<<grid, 256, GSM_TOTAL>>>(b0, b1, row0);

        finalize_kernel<<<(nrows * 32 + 255) / 256, 256>>>(sem, gam, bet, outA,
                                                           row0, nrows);
    }
}

// round 8
// speedup vs baseline: 1.1942x; 1.1942x over previous
#include <cuda_runtime.h>
#include <cuda_bf16.h>
#include <cstdint>

#define NA 100000
#define NB 100000
#define IN_DIM 256
#define OUT_DIM 256
#define NE 320000
#define LN_EPS 1e-5f

#define NBIN (2 * NA)            // 200000 (p, dst) bins
#define SCAN_B 512
#define NBLK ((NBIN + SCAN_B - 1) / SCAN_B)   // 391

// ---------------- scratch (device globals; no allocation allowed) -----------
__device__ float g_agg[(size_t)2 * NA * 256];        // per-path mean+bias
__device__ float g_cnt[NBIN];
__device__ __nv_bfloat16 g_Shi[(size_t)NBIN * 256];  // aggregated sums, bf16 hi
__device__ __nv_bfloat16 g_Slo[(size_t)NBIN * 256];  // bf16 lo residual
__device__ __nv_bfloat16 g_Wt_hi[512 * 256];         // Wcat^T [n][k]
__device__ __nv_bfloat16 g_Wt_lo[512 * 256];
__device__ int g_hist[NBIN];
__device__ int g_rowptr[NBIN];
__device__ int g_cursor[NBIN];
__device__ int g_elist[2 * NE];
__device__ int g_blocksums[SCAN_B];
__device__ int g_blockoff[SCAN_B];

// ---------------- helpers ----------------------------------------------------
__device__ __forceinline__ uint32_t smem_u32(const void* p) {
    uint32_t a;
    asm("{ .reg .u64 t; cvta.to.shared.u64 t, %1; cvt.u32.u64 %0, t; }" : "=r"(a) : "l"(p));
    return a;
}
__device__ __forceinline__ void ldsm_x4(uint32_t& r0, uint32_t& r1, uint32_t& r2,
                                        uint32_t& r3, uint32_t addr) {
    asm volatile("ldmatrix.sync.aligned.m8n8.x4.shared.b16 {%0,%1,%2,%3}, [%4];"
                 : "=r"(r0), "=r"(r1), "=r"(r2), "=r"(r3) : "r"(addr));
}
__device__ __forceinline__ void mma_bf16(float* c, const uint32_t* a, const uint32_t* b) {
    asm volatile("mma.sync.aligned.m16n8k16.row.col.f32.bf16.bf16.f32 "
                 "{%0,%1,%2,%3}, {%4,%5,%6,%7}, {%8,%9}, {%0,%1,%2,%3};"
                 : "+f"(c[0]), "+f"(c[1]), "+f"(c[2]), "+f"(c[3])
                 : "r"(a[0]), "r"(a[1]), "r"(a[2]), "r"(a[3]), "r"(b[0]), "r"(b[1]));
}
#define CP_ASYNC16(sm, gp) \
    asm volatile("cp.async.cg.shared.global [%0], [%1], 16;" \
                 :: "r"(sm), "l"(gp) : "memory")
#define CP_ASYNC16Z(sm, gp, sz) \
    asm volatile("cp.async.cg.shared.global [%0], [%1], 16, %2;" \
                 :: "r"(sm), "l"(gp), "r"(sz) : "memory")
#define CP_COMMIT() asm volatile("cp.async.commit_group;" ::: "memory")
#define CP_WAIT0()  asm volatile("cp.async.wait_group 0;" ::: "memory")
#define CP_WAIT1()  asm volatile("cp.async.wait_group 1;" ::: "memory")
#define CP_WAIT2()  asm volatile("cp.async.wait_group 2;" ::: "memory")

// ---------------- zero kernels ----------------------------------------------
__global__ __launch_bounds__(256) void zero_outB_kernel(float* __restrict__ outB) {
    size_t i = (size_t)blockIdx.x * 256 + threadIdx.x;
    const size_t n4 = (size_t)NB * OUT_DIM / 4;
    if (i < n4)
        reinterpret_cast<float4*>(outB)[i] = make_float4(0.f, 0.f, 0.f, 0.f);
}

__global__ __launch_bounds__(256) void zero_hist_kernel() {
    size_t i = (size_t)blockIdx.x * 256 + threadIdx.x;
    if (i < NBIN / 4)
        reinterpret_cast<int4*>(g_hist)[i] = make_int4(0, 0, 0, 0);
}

// ---------------- W split/transpose prep ------------------------------------
__global__ __launch_bounds__(256) void splitW_kernel(const float* __restrict__ W0,
                                                     const float* __restrict__ W1) {
    int n = blockIdx.x;
    int k = threadIdx.x;
    float w = (n < 256) ? W0[k * 256 + n] : W1[k * 256 + (n - 256)];
    __nv_bfloat16 h = __float2bfloat16_rn(w);
    float r = w - __bfloat162float(h);
    g_Wt_hi[n * 256 + k] = h;
    g_Wt_lo[n * 256 + k] = __float2bfloat16_rn(r);
}

// ---------------- CSR build --------------------------------------------------
__global__ __launch_bounds__(256) void hist_kernel(
    const int* __restrict__ ei0, const int* __restrict__ ei1)
{
    int i = blockIdx.x * 256 + threadIdx.x;
    if (i >= 2 * NE) return;
    int p = (i >= NE) ? 1 : 0;
    int e = i - p * NE;
    const int* __restrict__ ei = p ? ei1 : ei0;
    int dst = ei[e + NE];
    atomicAdd(&g_hist[p * NA + dst], 1);
}

__global__ __launch_bounds__(SCAN_B) void scanA_kernel() {
    __shared__ int sh[SCAN_B];
    int i = blockIdx.x * SCAN_B + threadIdx.x;
    sh[threadIdx.x] = (i < NBIN) ? g_hist[i] : 0;
    __syncthreads();
    for (int d = SCAN_B / 2; d > 0; d >>= 1) {
        if (threadIdx.x < d) sh[threadIdx.x] += sh[threadIdx.x + d];
        __syncthreads();
    }
    if (threadIdx.x == 0) g_blocksums[blockIdx.x] = sh[0];
}

__global__ __launch_bounds__(SCAN_B) void scanB_kernel() {
    __shared__ int sh[SCAN_B];
    int tid = threadIdx.x;
    int v = (tid < NBLK) ? g_blocksums[tid] : 0;
    sh[tid] = v;
    __syncthreads();
    for (int d = 1; d < SCAN_B; d <<= 1) {
        int t = (tid >= d) ? sh[tid - d] : 0;
        __syncthreads();
        sh[tid] += t;
        __syncthreads();
    }
    if (tid < NBLK) g_blockoff[tid] = sh[tid] - v;   // exclusive
}

__global__ __launch_bounds__(SCAN_B) void scanC_kernel() {
    __shared__ int sh[SCAN_B];
    int tid = threadIdx.x;
    int i = blockIdx.x * SCAN_B + tid;
    int v = (i < NBIN) ? g_hist[i] : 0;
    sh[tid] = v;
    __syncthreads();
    for (int d = 1; d < SCAN_B; d <<= 1) {
        int t = (tid >= d) ? sh[tid - d] : 0;
        __syncthreads();
        sh[tid] += t;
        __syncthreads();
    }
    if (i < NBIN) {
        int excl = sh[tid] - v + g_blockoff[blockIdx.x];
        g_rowptr[i] = excl;
        g_cursor[i] = excl;
        g_cnt[i] = (float)v;
    }
}

__global__ __launch_bounds__(256) void fill_kernel(
    const int* __restrict__ ei0, const int* __restrict__ ei1)
{
    int i = blockIdx.x * 256 + threadIdx.x;
    if (i >= 2 * NE) return;
    int p = (i >= NE) ? 1 : 0;
    int e = i - p * NE;
    const int* __restrict__ ei = p ? ei1 : ei0;
    int src = ei[e];
    int dst = ei[e + NE];
    int pos = atomicAdd(&g_cursor[p * NA + dst], 1);
    g_elist[pos] = src;
}

// ---------------- aggregate: warp per (p, dst); output bf16 hi/lo ------------
__global__ __launch_bounds__(256) void agg_kernel(const float* __restrict__ xB) {
    int w = (blockIdx.x * 256 + threadIdx.x) >> 5;
    int lane = threadIdx.x & 31;
    if (w >= NBIN) return;
    int start = g_rowptr[w];
    int deg = g_hist[w];

    float a[8] = {0.f, 0.f, 0.f, 0.f, 0.f, 0.f, 0.f, 0.f};

    int j = 0;
    for (; j + 4 <= deg; j += 4) {
        int s0 = __ldg(&g_elist[start + j]);
        int s1 = __ldg(&g_elist[start + j + 1]);
        int s2 = __ldg(&g_elist[start + j + 2]);
        int s3 = __ldg(&g_elist[start + j + 3]);
        const float4* r0 = reinterpret_cast<const float4*>(xB + (size_t)s0 * 256) + lane * 2;
        const float4* r1 = reinterpret_cast<const float4*>(xB + (size_t)s1 * 256) + lane * 2;
        const float4* r2 = reinterpret_cast<const float4*>(xB + (size_t)s2 * 256) + lane * 2;
        const float4* r3 = reinterpret_cast<const float4*>(xB + (size_t)s3 * 256) + lane * 2;
        float4 v0a = r0[0], v0b = r0[1];
        float4 v1a = r1[0], v1b = r1[1];
        float4 v2a = r2[0], v2b = r2[1];
        float4 v3a = r3[0], v3b = r3[1];
        a[0] += v0a.x + v1a.x + v2a.x + v3a.x;
        a[1] += v0a.y + v1a.y + v2a.y + v3a.y;
        a[2] += v0a.z + v1a.z + v2a.z + v3a.z;
        a[3] += v0a.w + v1a.w + v2a.w + v3a.w;
        a[4] += v0b.x + v1b.x + v2b.x + v3b.x;
        a[5] += v0b.y + v1b.y + v2b.y + v3b.y;
        a[6] += v0b.z + v1b.z + v2b.z + v3b.z;
        a[7] += v0b.w + v1b.w + v2b.w + v3b.w;
    }
    for (; j < deg; j++) {
        int src = __ldg(&g_elist[start + j]);
        const float4* r4 = reinterpret_cast<const float4*>(xB + (size_t)src * 256) + lane * 2;
        float4 v0 = r4[0], v1 = r4[1];
        a[0] += v0.x; a[1] += v0.y; a[2] += v0.z; a[3] += v0.w;
        a[4] += v1.x; a[5] += v1.y; a[6] += v1.z; a[7] += v1.w;
    }

    uint4 hv, lv;
    {
        __nv_bfloat162 h0 = __floats2bfloat162_rn(a[0], a[1]);
        __nv_bfloat162 h1 = __floats2bfloat162_rn(a[2], a[3]);
        __nv_bfloat162 h2 = __floats2bfloat162_rn(a[4], a[5]);
        __nv_bfloat162 h3 = __floats2bfloat162_rn(a[6], a[7]);
        __nv_bfloat162 l0 = __floats2bfloat162_rn(a[0] - __bfloat162float(h0.x),
                                                  a[1] - __bfloat162float(h0.y));
        __nv_bfloat162 l1 = __floats2bfloat162_rn(a[2] - __bfloat162float(h1.x),
                                                  a[3] - __bfloat162float(h1.y));
        __nv_bfloat162 l2 = __floats2bfloat162_rn(a[4] - __bfloat162float(h2.x),
                                                  a[5] - __bfloat162float(h2.y));
        __nv_bfloat162 l3 = __floats2bfloat162_rn(a[6] - __bfloat162float(h3.x),
                                                  a[7] - __bfloat162float(h3.y));
        hv.x = *reinterpret_cast<uint32_t*>(&h0); hv.y = *reinterpret_cast<uint32_t*>(&h1);
        hv.z = *reinterpret_cast<uint32_t*>(&h2); hv.w = *reinterpret_cast<uint32_t*>(&h3);
        lv.x = *reinterpret_cast<uint32_t*>(&l0); lv.y = *reinterpret_cast<uint32_t*>(&l1);
        lv.z = *reinterpret_cast<uint32_t*>(&l2); lv.w = *reinterpret_cast<uint32_t*>(&l3);
    }
    *reinterpret_cast<uint4*>(g_Shi + (size_t)w * 256 + lane * 8) = hv;
    *reinterpret_cast<uint4*>(g_Slo + (size_t)w * 256 + lane * 8) = lv;
}

// ---------------- HMMA GEMM: agg = (S @ W)/cnt + b --------------------------
// grid (4, 782): bx = p*2+h (fast -> A-tile L2 reuse), by = m-tile.
// K-chunk 32, 3-stage cp.async pipeline. Stage = [A 16KB | B 16KB] = 32KB.
#define GBUF 32768
#define GSM_TOTAL (3 * GBUF)

__device__ __forceinline__ void gemm_issue(
    uint32_t sb, int tid, int m0,
    const __nv_bfloat16* __restrict__ Ahi, const __nv_bfloat16* __restrict__ Alo,
    const __nv_bfloat16* __restrict__ Bhi, const __nv_bfloat16* __restrict__ Blo,
    int kc)
{
#pragma unroll
    for (int l = 0; l < 4; l++) {
        int ulin = l * 256 + tid;
        int r = ulin >> 3, u = ulin & 7;
        int grow = m0 + r;
        int ok = (grow < NA) ? 16 : 0;
        int grc = (grow < NA) ? grow : (NA - 1);
        uint32_t dst = sb + (uint32_t)(r * 128 + ((u ^ (r & 7)) << 4));
        const __nv_bfloat16* src = (u < 4)
            ? (Ahi + (size_t)grc * 256 + kc * 32 + (u & 3) * 8)
            : (Alo + (size_t)grc * 256 + kc * 32 + (u & 3) * 8);
        CP_ASYNC16Z(dst, src, ok);
    }
#pragma unroll
    for (int l = 0; l < 4; l++) {
        int ulin = l * 256 + tid;
        int n = ulin >> 3, u = ulin & 7;
        uint32_t dst = sb + 16384u + (uint32_t)(n * 128 + ((u ^ (n & 7)) << 4));
        const __nv_bfloat16* src = (u < 4)
            ? (Bhi + (size_t)n * 256 + kc * 32 + (u & 3) * 8)
            : (Blo + (size_t)n * 256 + kc * 32 + (u & 3) * 8);
        CP_ASYNC16(dst, src);
    }
    CP_COMMIT();
}

__global__ __launch_bounds__(256, 2) void gemm_mma_kernel(
    const float* __restrict__ b0, const float* __restrict__ b1)
{
    extern __shared__ char smem[];
    const uint32_t sbase = smem_u32(smem);
    const int tid = threadIdx.x, lane = tid & 31, wid = tid >> 5;
    const int wm = wid & 3;
    const int wn = wid >> 2;
    const int p = blockIdx.x >> 1, h = blockIdx.x & 1;
    const int m0 = blockIdx.y * 128;

    const __nv_bfloat16* __restrict__ Ahi = g_Shi + (size_t)p * NA * 256;
    const __nv_bfloat16* __restrict__ Alo = g_Slo + (size_t)p * NA * 256;
    const __nv_bfloat16* __restrict__ Bhi = g_Wt_hi + (size_t)(p * 256 + h * 128) * 256;
    const __nv_bfloat16* __restrict__ Blo = g_Wt_lo + (size_t)(p * 256 + h * 128) * 256;

    float c[2][8][4];
#pragma unroll
    for (int mt = 0; mt < 2; mt++)
#pragma unroll
        for (int n8 = 0; n8 < 8; n8++)
#pragma unroll
            for (int q = 0; q < 4; q++) c[mt][n8][q] = 0.f;

    const int am = lane & 15;
    const int aoff = lane >> 4;
    const int asw = am & 7;
    const int bn = (lane & 7) | ((lane & 16) >> 1);
    const int boff = (lane >> 3) & 1;
    const int bsw = bn & 7;

    gemm_issue(sbase, tid, m0, Ahi, Alo, Bhi, Blo, 0);
    gemm_issue(sbase + GBUF, tid, m0, Ahi, Alo, Bhi, Blo, 1);

    for (int kc = 0; kc < 8; kc++) {
        if (kc + 2 < 8) {
            gemm_issue(sbase + ((kc + 2) % 3) * GBUF, tid, m0, Ahi, Alo, Bhi, Blo, kc + 2);
            CP_WAIT2();
        } else if (kc + 1 < 8) {
            CP_WAIT1();
        } else {
            CP_WAIT0();
        }
        __syncthreads();
        const uint32_t sb = sbase + (kc % 3) * GBUF;

#pragma unroll
        for (int s = 0; s < 2; s++) {
            const int uhi = (s << 1) | aoff;
            uint32_t ah[2][4], al[2][4];
#pragma unroll
            for (int mt = 0; mt < 2; mt++) {
                int arow = wm * 32 + mt * 16 + am;
                uint32_t rb = sb + (uint32_t)(arow * 128);
                ldsm_x4(ah[mt][0], ah[mt][1], ah[mt][2], ah[mt][3],
                        rb + ((uhi ^ asw) << 4));
                ldsm_x4(al[mt][0], al[mt][1], al[mt][2], al[mt][3],
                        rb + (((4 | uhi) ^ asw) << 4));
            }
            const int vhi = (s << 1) | boff;
#pragma unroll
            for (int g = 0; g < 4; g++) {
                int brow = wn * 64 + g * 16 + bn;
                uint32_t rb = sb + 16384u + (uint32_t)(brow * 128);
                uint32_t bh[4], bl[4];
                ldsm_x4(bh[0], bh[1], bh[2], bh[3], rb + ((vhi ^ bsw) << 4));
                ldsm_x4(bl[0], bl[1], bl[2], bl[3], rb + (((4 | vhi) ^ bsw) << 4));
#pragma unroll
                for (int mt = 0; mt < 2; mt++) {
                    mma_bf16(c[mt][2 * g],     ah[mt], &bh[0]);
                    mma_bf16(c[mt][2 * g],     ah[mt], &bl[0]);
                    mma_bf16(c[mt][2 * g],     al[mt], &bh[0]);
                    mma_bf16(c[mt][2 * g + 1], ah[mt], &bh[2]);
                    mma_bf16(c[mt][2 * g + 1], ah[mt], &bl[2]);
                    mma_bf16(c[mt][2 * g + 1], al[mt], &bh[2]);
                }
            }
        }
        __syncthreads();
    }

    // ---- epilogue: mean + bias -> g_agg ------------------------------------
    const float* __restrict__ bias = p ? b1 : b0;
    float* __restrict__ dst = g_agg + (size_t)p * NA * 256;
#pragma unroll
    for (int mt = 0; mt < 2; mt++) {
#pragma unroll
        for (int rr = 0; rr < 2; rr++) {
            int row = m0 + wm * 32 + mt * 16 + rr * 8 + (lane >> 2);
            if (row >= NA) continue;
            float cv = g_cnt[p * NA + row];
            float inv = cv > 0.f ? 1.f / cv : 0.f;
            float bf = cv > 0.f ? 1.f : 0.f;
            float* orow = dst + (size_t)row * 256;
#pragma unroll
            for (int n8 = 0; n8 < 8; n8++) {
                int col = h * 128 + wn * 64 + n8 * 8 + (lane & 3) * 2;
                float2 o;
                o.x = c[mt][n8][rr * 2 + 0] * inv + bias[col] * bf;
                o.y = c[mt][n8][rr * 2 + 1] * inv + bias[col + 1] * bf;
                *reinterpret_cast<float2*>(orow + col) = o;
            }
        }
    }
}

// ---------------- finalize: one warp per destination row --------------------
__global__ __launch_bounds__(256) void finalize_kernel(
    const float* __restrict__ sem, const float* __restrict__ gamma,
    const float* __restrict__ beta, float* __restrict__ outA)
{
    int n = (blockIdx.x * 256 + threadIdx.x) >> 5;
    int lane = threadIdx.x & 31;
    if (n >= NA) return;
    int base = lane * 8;

    const float* a0p = g_agg + (size_t)n * 256;
    const float* a1p = g_agg + ((size_t)NA + n) * 256;

    float a0[8], a1[8], sv[8];
    *reinterpret_cast<float4*>(&a0[0]) = *reinterpret_cast<const float4*>(a0p + base);
    *reinterpret_cast<float4*>(&a0[4]) = *reinterpret_cast<const float4*>(a0p + base + 4);
    *reinterpret_cast<float4*>(&a1[0]) = *reinterpret_cast<const float4*>(a1p + base);
    *reinterpret_cast<float4*>(&a1[4]) = *reinterpret_cast<const float4*>(a1p + base + 4);
    *reinterpret_cast<float4*>(&sv[0]) = *reinterpret_cast<const float4*>(sem + base);
    *reinterpret_cast<float4*>(&sv[4]) = *reinterpret_cast<const float4*>(sem + base + 4);

    float s0 = 0.f, s1 = 0.f;
#pragma unroll
    for (int i = 0; i < 8; i++) {
        s0 += tanhf(a0[i]) * sv[i];
        s1 += tanhf(a1[i]) * sv[i];
    }
#pragma unroll
    for (int o = 16; o > 0; o >>= 1) {
        s0 += __shfl_xor_sync(0xffffffffu, s0, o);
        s1 += __shfl_xor_sync(0xffffffffu, s1, o);
    }
    float m = fmaxf(s0, s1);
    float e0 = __expf(s0 - m), e1 = __expf(s1 - m);
    float w0 = e0 / (e0 + e1);
    float w1 = 1.0f - w0;

    float f[8];
    float sum = 0.f, sq = 0.f;
#pragma unroll
    for (int i = 0; i < 8; i++) {
        f[i] = fmaxf(w0 * a0[i] + w1 * a1[i], 0.f);
        sum += f[i];
        sq  += f[i] * f[i];
    }
#pragma unroll
    for (int o = 16; o > 0; o >>= 1) {
        sum += __shfl_xor_sync(0xffffffffu, sum, o);
        sq  += __shfl_xor_sync(0xffffffffu, sq, o);
    }
    float mu  = sum * (1.0f / 256.0f);
    float var = sq * (1.0f / 256.0f) - mu * mu;
    float rstd = rsqrtf(var + LN_EPS);

    float gm[8], bt[8];
    *reinterpret_cast<float4*>(&gm[0]) = *reinterpret_cast<const float4*>(gamma + base);
    *reinterpret_cast<float4*>(&gm[4]) = *reinterpret_cast<const float4*>(gamma + base + 4);
    *reinterpret_cast<float4*>(&bt[0]) = *reinterpret_cast<const float4*>(beta + base);
    *reinterpret_cast<float4*>(&bt[4]) = *reinterpret_cast<const float4*>(beta + base + 4);

    float o8[8];
#pragma unroll
    for (int i = 0; i < 8; i++)
        o8[i] = (f[i] - mu) * rstd * gm[i] + bt[i];

    float* op = outA + (size_t)n * 256 + base;
    *reinterpret_cast<float4*>(op)     = *reinterpret_cast<float4*>(&o8[0]);
    *reinterpret_cast<float4*>(op + 4) = *reinterpret_cast<float4*>(&o8[4]);
}

// ---------------- launch ----------------------------------------------------
extern "C" void kernel_launch(void* const* d_in, const int* in_sizes, int n_in,
                              void* d_out, int out_size)
{
    const float* x_B  = (const float*)d_in[1];
    const int*   ei0  = (const int*)d_in[2];
    const int*   ei1  = (const int*)d_in[3];
    const float* W0   = (const float*)d_in[4];
    const float* b0   = (const float*)d_in[5];
    const float* W1   = (const float*)d_in[6];
    const float* b1   = (const float*)d_in[7];
    const float* sem  = (const float*)d_in[8];
    const float* gam  = (const float*)d_in[9];
    const float* bet  = (const float*)d_in[10];

    float* outA = (float*)d_out;
    float* outB = outA + (size_t)NA * OUT_DIM;

    cudaFuncSetAttribute(gemm_mma_kernel,
                         cudaFuncAttributeMaxDynamicSharedMemorySize, GSM_TOTAL);

    // Side stream: zero_outB + splitW overlap with the CSR build chain.
    cudaStream_t s2;
    cudaEvent_t eFork, eJoin;
    cudaStreamCreateWithFlags(&s2, cudaStreamNonBlocking);
    cudaEventCreateWithFlags(&eFork, cudaEventDisableTiming);
    cudaEventCreateWithFlags(&eJoin, cudaEventDisableTiming);

    // main: zero hist (needed by hist_kernel)
    zero_hist_kernel<<<(NBIN / 4 + 255) / 256, 256>>>();

    // fork side chain from the main (capture) stream
    cudaEventRecord(eFork, 0);
    cudaStreamWaitEvent(s2, eFork, 0);
    zero_outB_kernel<<<(int)(((size_t)NB * OUT_DIM / 4 + 255) / 256), 256, 0, s2>>>(outB);
    splitW_kernel<<<512, 256, 0, s2>>>(W0, W1);
    cudaEventRecord(eJoin, s2);

    // main: CSR build chain (independent of side chain)
    hist_kernel<<<(2 * NE + 255) / 256, 256>>>(ei0, ei1);
    scanA_kernel<<<NBLK, SCAN_B>>>();
    scanB_kernel<<<1, SCAN_B>>>();
    scanC_kernel<<<NBLK, SCAN_B>>>();
    fill_kernel<<<(2 * NE + 255) / 256, 256>>>(ei0, ei1);

    // gather-aggregate -> bf16 hi/lo sums
    agg_kernel<<<(NBIN * 32 + 255) / 256, 256>>>(x_B);

    // join side chain (gemm needs splitW; outB zero must be in graph)
    cudaStreamWaitEvent(0, eJoin, 0);

    // HMMA GEMM: agg = (S @ W)/cnt + b
    {
        dim3 grid(4, (NA + 127) / 128);
        gemm_mma_kernel<<<grid, 256, GSM_TOTAL>>>(b0, b1);
    }
    // semantic attention + relu + layernorm
    finalize_kernel<<<(NA * 32 + 255) / 256, 256>>>(sem, gam, bet, outA);

    cudaEventDestroy(eFork);
    cudaEventDestroy(eJoin);
    cudaStreamDestroy(s2);
}

// round 9
// speedup vs baseline: 1.4291x; 1.1966x over previous
#include <cuda_runtime.h>
#include <cuda_fp16.h>
#include <cstdint>

#define NA 100000
#define NB 100000
#define IN_DIM 256
#define OUT_DIM 256
#define NE 320000
#define LN_EPS 1e-5f

#define NBIN (2 * NA)            // 200000 (p, dst) bins
#define SCAN_B 512
#define NBLK ((NBIN + SCAN_B - 1) / SCAN_B)   // 391

// ---------------- scratch (device globals; no allocation allowed) -----------
__device__ float g_agg[(size_t)2 * NA * 256];        // per-path mean+bias
__device__ float g_cnt[NBIN];                        // 1.0 if deg>0 else 0.0
__device__ __half g_Sh[(size_t)NBIN * 256];          // per-bin MEAN, fp16
__device__ __half g_Wt_hi[512 * 256];                // Wcat^T [n][k], fp16 hi
__device__ __half g_Wt_lo[512 * 256];                // fp16 lo residual
__device__ int g_hist[NBIN];
__device__ int g_rowptr[NBIN];
__device__ int g_cursor[NBIN];
__device__ int g_elist[2 * NE];
__device__ int g_blocksums[SCAN_B];
__device__ int g_blockoff[SCAN_B];

// ---------------- helpers ----------------------------------------------------
__device__ __forceinline__ uint32_t smem_u32(const void* p) {
    uint32_t a;
    asm("{ .reg .u64 t; cvta.to.shared.u64 t, %1; cvt.u32.u64 %0, t; }" : "=r"(a) : "l"(p));
    return a;
}
__device__ __forceinline__ void ldsm_x4(uint32_t& r0, uint32_t& r1, uint32_t& r2,
                                        uint32_t& r3, uint32_t addr) {
    asm volatile("ldmatrix.sync.aligned.m8n8.x4.shared.b16 {%0,%1,%2,%3}, [%4];"
                 : "=r"(r0), "=r"(r1), "=r"(r2), "=r"(r3) : "r"(addr));
}
__device__ __forceinline__ void mma_fp16(float* c, const uint32_t* a, const uint32_t* b) {
    asm volatile("mma.sync.aligned.m16n8k16.row.col.f32.f16.f16.f32 "
                 "{%0,%1,%2,%3}, {%4,%5,%6,%7}, {%8,%9}, {%0,%1,%2,%3};"
                 : "+f"(c[0]), "+f"(c[1]), "+f"(c[2]), "+f"(c[3])
                 : "r"(a[0]), "r"(a[1]), "r"(a[2]), "r"(a[3]), "r"(b[0]), "r"(b[1]));
}
#define CP_ASYNC16(sm, gp) \
    asm volatile("cp.async.cg.shared.global [%0], [%1], 16;" \
                 :: "r"(sm), "l"(gp) : "memory")
#define CP_ASYNC16Z(sm, gp, sz) \
    asm volatile("cp.async.cg.shared.global [%0], [%1], 16, %2;" \
                 :: "r"(sm), "l"(gp), "r"(sz) : "memory")
#define CP_COMMIT() asm volatile("cp.async.commit_group;" ::: "memory")
#define CP_WAIT0()  asm volatile("cp.async.wait_group 0;" ::: "memory")
#define CP_WAIT1()  asm volatile("cp.async.wait_group 1;" ::: "memory")

// ---------------- zero hist ---------------------------------------------------
__global__ __launch_bounds__(256) void zero_hist_kernel() {
    size_t i = (size_t)blockIdx.x * 256 + threadIdx.x;
    if (i < NBIN / 4)
        reinterpret_cast<int4*>(g_hist)[i] = make_int4(0, 0, 0, 0);
}

// ---------------- W split/transpose prep ------------------------------------
__global__ __launch_bounds__(256) void splitW_kernel(const float* __restrict__ W0,
                                                     const float* __restrict__ W1) {
    int n = blockIdx.x;
    int k = threadIdx.x;
    float w = (n < 256) ? W0[k * 256 + n] : W1[k * 256 + (n - 256)];
    __half h = __float2half_rn(w);
    float r = w - __half2float(h);
    g_Wt_hi[n * 256 + k] = h;
    g_Wt_lo[n * 256 + k] = __float2half_rn(r);
}

// ---------------- CSR build --------------------------------------------------
__global__ __launch_bounds__(256) void hist_kernel(
    const int* __restrict__ ei0, const int* __restrict__ ei1)
{
    int i = blockIdx.x * 256 + threadIdx.x;
    if (i >= 2 * NE) return;
    int p = (i >= NE) ? 1 : 0;
    int e = i - p * NE;
    const int* __restrict__ ei = p ? ei1 : ei0;
    int dst = ei[e + NE];
    atomicAdd(&g_hist[p * NA + dst], 1);
}

__global__ __launch_bounds__(SCAN_B) void scanA_kernel() {
    __shared__ int sh[SCAN_B];
    int i = blockIdx.x * SCAN_B + threadIdx.x;
    sh[threadIdx.x] = (i < NBIN) ? g_hist[i] : 0;
    __syncthreads();
    for (int d = SCAN_B / 2; d > 0; d >>= 1) {
        if (threadIdx.x < d) sh[threadIdx.x] += sh[threadIdx.x + d];
        __syncthreads();
    }
    if (threadIdx.x == 0) g_blocksums[blockIdx.x] = sh[0];
}

__global__ __launch_bounds__(SCAN_B) void scanB_kernel() {
    __shared__ int sh[SCAN_B];
    int tid = threadIdx.x;
    int v = (tid < NBLK) ? g_blocksums[tid] : 0;
    sh[tid] = v;
    __syncthreads();
    for (int d = 1; d < SCAN_B; d <<= 1) {
        int t = (tid >= d) ? sh[tid - d] : 0;
        __syncthreads();
        sh[tid] += t;
        __syncthreads();
    }
    if (tid < NBLK) g_blockoff[tid] = sh[tid] - v;   // exclusive
}

__global__ __launch_bounds__(SCAN_B) void scanC_kernel() {
    __shared__ int sh[SCAN_B];
    int tid = threadIdx.x;
    int i = blockIdx.x * SCAN_B + tid;
    int v = (i < NBIN) ? g_hist[i] : 0;
    sh[tid] = v;
    __syncthreads();
    for (int d = 1; d < SCAN_B; d <<= 1) {
        int t = (tid >= d) ? sh[tid - d] : 0;
        __syncthreads();
        sh[tid] += t;
        __syncthreads();
    }
    if (i < NBIN) {
        int excl = sh[tid] - v + g_blockoff[blockIdx.x];
        g_rowptr[i] = excl;
        g_cursor[i] = excl;
        g_cnt[i] = (v > 0) ? 1.0f : 0.0f;
    }
}

__global__ __launch_bounds__(256) void fill_kernel(
    const int* __restrict__ ei0, const int* __restrict__ ei1)
{
    int i = blockIdx.x * 256 + threadIdx.x;
    if (i >= 2 * NE) return;
    int p = (i >= NE) ? 1 : 0;
    int e = i - p * NE;
    const int* __restrict__ ei = p ? ei1 : ei0;
    int src = ei[e];
    int dst = ei[e + NE];
    int pos = atomicAdd(&g_cursor[p * NA + dst], 1);
    g_elist[pos] = src;
}

// ---------------- aggregate: warp per bin; mean -> fp16 ----------------------
__global__ __launch_bounds__(256) void agg_kernel(const float* __restrict__ xB) {
    int w = (blockIdx.x * 256 + threadIdx.x) >> 5;
    int lane = threadIdx.x & 31;
    if (w >= NBIN) return;
    int start = g_rowptr[w];
    int deg = g_hist[w];

    float a[8] = {0.f, 0.f, 0.f, 0.f, 0.f, 0.f, 0.f, 0.f};

    int j = 0;
    for (; j + 4 <= deg; j += 4) {
        int s0 = __ldg(&g_elist[start + j]);
        int s1 = __ldg(&g_elist[start + j + 1]);
        int s2 = __ldg(&g_elist[start + j + 2]);
        int s3 = __ldg(&g_elist[start + j + 3]);
        const float4* r0 = reinterpret_cast<const float4*>(xB + (size_t)s0 * 256) + lane * 2;
        const float4* r1 = reinterpret_cast<const float4*>(xB + (size_t)s1 * 256) + lane * 2;
        const float4* r2 = reinterpret_cast<const float4*>(xB + (size_t)s2 * 256) + lane * 2;
        const float4* r3 = reinterpret_cast<const float4*>(xB + (size_t)s3 * 256) + lane * 2;
        float4 v0a = r0[0], v0b = r0[1];
        float4 v1a = r1[0], v1b = r1[1];
        float4 v2a = r2[0], v2b = r2[1];
        float4 v3a = r3[0], v3b = r3[1];
        a[0] += v0a.x + v1a.x + v2a.x + v3a.x;
        a[1] += v0a.y + v1a.y + v2a.y + v3a.y;
        a[2] += v0a.z + v1a.z + v2a.z + v3a.z;
        a[3] += v0a.w + v1a.w + v2a.w + v3a.w;
        a[4] += v0b.x + v1b.x + v2b.x + v3b.x;
        a[5] += v0b.y + v1b.y + v2b.y + v3b.y;
        a[6] += v0b.z + v1b.z + v2b.z + v3b.z;
        a[7] += v0b.w + v1b.w + v2b.w + v3b.w;
    }
    for (; j < deg; j++) {
        int src = __ldg(&g_elist[start + j]);
        const float4* r4 = reinterpret_cast<const float4*>(xB + (size_t)src * 256) + lane * 2;
        float4 v0 = r4[0], v1 = r4[1];
        a[0] += v0.x; a[1] += v0.y; a[2] += v0.z; a[3] += v0.w;
        a[4] += v1.x; a[5] += v1.y; a[6] += v1.z; a[7] += v1.w;
    }

    float inv = (deg > 0) ? 1.0f / (float)deg : 0.0f;
    __half2 h0 = __floats2half2_rn(a[0] * inv, a[1] * inv);
    __half2 h1 = __floats2half2_rn(a[2] * inv, a[3] * inv);
    __half2 h2 = __floats2half2_rn(a[4] * inv, a[5] * inv);
    __half2 h3 = __floats2half2_rn(a[6] * inv, a[7] * inv);
    uint4 hv;
    hv.x = *reinterpret_cast<uint32_t*>(&h0);
    hv.y = *reinterpret_cast<uint32_t*>(&h1);
    hv.z = *reinterpret_cast<uint32_t*>(&h2);
    hv.w = *reinterpret_cast<uint32_t*>(&h3);
    *reinterpret_cast<uint4*>(g_Sh + (size_t)w * 256 + lane * 8) = hv;
}

// ---------------- HMMA GEMM: agg = mean @ W + b --------------------------------
// grid (4, 782): bx = p*2+h, by = m-tile. A fp16 (quantized), B fp16 hi+lo.
// K-chunk 64: stage = [A 16KB | B1 16KB | B2 16KB] = 48KB; 2 stages = 96KB.
#define GBUF 49152
#define GSM_TOTAL (2 * GBUF)

__device__ __forceinline__ void gemm_issue(
    uint32_t sb, int tid, int m0,
    const __half* __restrict__ Ah,
    const __half* __restrict__ Bhi, const __half* __restrict__ Blo,
    int kc)
{
    // A: 128 rows x 64 k fp16 = 1024 x 16B units
#pragma unroll
    for (int l = 0; l < 4; l++) {
        int idx = l * 256 + tid;
        int r = idx >> 3, u = idx & 7;
        int grow = m0 + r;
        int ok = (grow < NA) ? 16 : 0;
        int grc = (grow < NA) ? grow : (NA - 1);
        uint32_t dst = sb + (uint32_t)(r * 128 + ((u ^ (r & 7)) << 4));
        const __half* src = Ah + (size_t)grc * 256 + kc * 64 + u * 8;
        CP_ASYNC16Z(dst, src, ok);
    }
    // B: 2 sub-tiles (k 0-31, 32-63), each 128 rows x [hi 64B | lo 64B]
#pragma unroll
    for (int l = 0; l < 8; l++) {
        int idx = l * 256 + tid;
        int sub = idx >> 10, rem = idx & 1023;
        int n = rem >> 3, u = rem & 7;
        uint32_t dst = sb + 16384u + (uint32_t)(sub * 16384 + n * 128 + ((u ^ (n & 7)) << 4));
        const __half* base = (u < 4) ? Bhi : Blo;
        const __half* src = base + (size_t)n * 256 + kc * 64 + sub * 32 + (u & 3) * 8;
        CP_ASYNC16(dst, src);
    }
    CP_COMMIT();
}

__global__ __launch_bounds__(256, 2) void gemm_mma_kernel(
    const float* __restrict__ b0, const float* __restrict__ b1)
{
    extern __shared__ char smem[];
    const uint32_t sbase = smem_u32(smem);
    const int tid = threadIdx.x, lane = tid & 31, wid = tid >> 5;
    const int wm = wid & 3;
    const int wn = wid >> 2;
    const int p = blockIdx.x >> 1, h = blockIdx.x & 1;
    const int m0 = blockIdx.y * 128;

    const __half* __restrict__ Ah  = g_Sh + (size_t)p * NA * 256;
    const __half* __restrict__ Bhi = g_Wt_hi + (size_t)(p * 256 + h * 128) * 256;
    const __half* __restrict__ Blo = g_Wt_lo + (size_t)(p * 256 + h * 128) * 256;

    float c[2][8][4];
#pragma unroll
    for (int mt = 0; mt < 2; mt++)
#pragma unroll
        for (int n8 = 0; n8 < 8; n8++)
#pragma unroll
            for (int q = 0; q < 4; q++) c[mt][n8][q] = 0.f;

    const int am = lane & 15;
    const int aoff = lane >> 4;
    const int asw = am & 7;
    const int bn = (lane & 7) | ((lane & 16) >> 1);
    const int boff = (lane >> 3) & 1;
    const int bsw = bn & 7;

    gemm_issue(sbase, tid, m0, Ah, Bhi, Blo, 0);

    for (int kc = 0; kc < 4; kc++) {
        if (kc < 3) {
            gemm_issue(sbase + ((kc + 1) & 1) * GBUF, tid, m0, Ah, Bhi, Blo, kc + 1);
            CP_WAIT1();
        } else {
            CP_WAIT0();
        }
        __syncthreads();
        const uint32_t sb = sbase + (kc & 1) * GBUF;

#pragma unroll
        for (int s = 0; s < 4; s++) {
            const int unit = (s << 1) | aoff;
            uint32_t ah[2][4];
#pragma unroll
            for (int mt = 0; mt < 2; mt++) {
                int arow = wm * 32 + mt * 16 + am;
                ldsm_x4(ah[mt][0], ah[mt][1], ah[mt][2], ah[mt][3],
                        sb + (uint32_t)(arow * 128) + ((unit ^ asw) << 4));
            }
            const int sub = s >> 1;
            const int vhi = ((s & 1) << 1) | boff;
#pragma unroll
            for (int g = 0; g < 4; g++) {
                int brow = wn * 64 + g * 16 + bn;
                uint32_t rb = sb + 16384u + (uint32_t)(sub * 16384 + brow * 128);
                uint32_t bh[4], bl[4];
                ldsm_x4(bh[0], bh[1], bh[2], bh[3], rb + ((vhi ^ bsw) << 4));
                ldsm_x4(bl[0], bl[1], bl[2], bl[3], rb + (((4 | vhi) ^ bsw) << 4));
#pragma unroll
                for (int mt = 0; mt < 2; mt++) {
                    mma_fp16(c[mt][2 * g],     ah[mt], &bh[0]);
                    mma_fp16(c[mt][2 * g],     ah[mt], &bl[0]);
                    mma_fp16(c[mt][2 * g + 1], ah[mt], &bh[2]);
                    mma_fp16(c[mt][2 * g + 1], ah[mt], &bl[2]);
                }
            }
        }
        __syncthreads();
    }

    // ---- epilogue: + bias flag -> g_agg ------------------------------------
    const float* __restrict__ bias = p ? b1 : b0;
    float* __restrict__ dst = g_agg + (size_t)p * NA * 256;
#pragma unroll
    for (int mt = 0; mt < 2; mt++) {
#pragma unroll
        for (int rr = 0; rr < 2; rr++) {
            int row = m0 + wm * 32 + mt * 16 + rr * 8 + (lane >> 2);
            if (row >= NA) continue;
            float bf = g_cnt[p * NA + row];
            float* orow = dst + (size_t)row * 256;
#pragma unroll
            for (int n8 = 0; n8 < 8; n8++) {
                int col = h * 128 + wn * 64 + n8 * 8 + (lane & 3) * 2;
                float2 o;
                o.x = c[mt][n8][rr * 2 + 0] + bias[col] * bf;
                o.y = c[mt][n8][rr * 2 + 1] + bias[col + 1] * bf;
                *reinterpret_cast<float2*>(orow + col) = o;
            }
        }
    }
}

// ---------------- finalize + outB zeroing ------------------------------------
#define FIN_BLOCKS ((NA * 32 + 255) / 256)                    // 12500
#define ZB_BLOCKS  ((int)(((size_t)NB * OUT_DIM / 4 + 255) / 256))  // 25000

__global__ __launch_bounds__(256) void finalize_kernel(
    const float* __restrict__ sem, const float* __restrict__ gamma,
    const float* __restrict__ beta, float* __restrict__ outA,
    float* __restrict__ outB)
{
    if (blockIdx.x >= FIN_BLOCKS) {
        size_t i = (size_t)(blockIdx.x - FIN_BLOCKS) * 256 + threadIdx.x;
        if (i < (size_t)NB * OUT_DIM / 4)
            reinterpret_cast<float4*>(outB)[i] = make_float4(0.f, 0.f, 0.f, 0.f);
        return;
    }
    int n = (blockIdx.x * 256 + threadIdx.x) >> 5;
    int lane = threadIdx.x & 31;
    if (n >= NA) return;
    int base = lane * 8;

    const float* a0p = g_agg + (size_t)n * 256;
    const float* a1p = g_agg + ((size_t)NA + n) * 256;

    float a0[8], a1[8], sv[8];
    *reinterpret_cast<float4*>(&a0[0]) = *reinterpret_cast<const float4*>(a0p + base);
    *reinterpret_cast<float4*>(&a0[4]) = *reinterpret_cast<const float4*>(a0p + base + 4);
    *reinterpret_cast<float4*>(&a1[0]) = *reinterpret_cast<const float4*>(a1p + base);
    *reinterpret_cast<float4*>(&a1[4]) = *reinterpret_cast<const float4*>(a1p + base + 4);
    *reinterpret_cast<float4*>(&sv[0]) = *reinterpret_cast<const float4*>(sem + base);
    *reinterpret_cast<float4*>(&sv[4]) = *reinterpret_cast<const float4*>(sem + base + 4);

    float s0 = 0.f, s1 = 0.f;
#pragma unroll
    for (int i = 0; i < 8; i++) {
        s0 += tanhf(a0[i]) * sv[i];
        s1 += tanhf(a1[i]) * sv[i];
    }
#pragma unroll
    for (int o = 16; o > 0; o >>= 1) {
        s0 += __shfl_xor_sync(0xffffffffu, s0, o);
        s1 += __shfl_xor_sync(0xffffffffu, s1, o);
    }
    float m = fmaxf(s0, s1);
    float e0 = __expf(s0 - m), e1 = __expf(s1 - m);
    float w0 = e0 / (e0 + e1);
    float w1 = 1.0f - w0;

    float f[8];
    float sum = 0.f, sq = 0.f;
#pragma unroll
    for (int i = 0; i < 8; i++) {
        f[i] = fmaxf(w0 * a0[i] + w1 * a1[i], 0.f);
        sum += f[i];
        sq  += f[i] * f[i];
    }
#pragma unroll
    for (int o = 16; o > 0; o >>= 1) {
        sum += __shfl_xor_sync(0xffffffffu, sum, o);
        sq  += __shfl_xor_sync(0xffffffffu, sq, o);
    }
    float mu  = sum * (1.0f / 256.0f);
    float var = sq * (1.0f / 256.0f) - mu * mu;
    float rstd = rsqrtf(var + LN_EPS);

    float gm[8], bt[8];
    *reinterpret_cast<float4*>(&gm[0]) = *reinterpret_cast<const float4*>(gamma + base);
    *reinterpret_cast<float4*>(&gm[4]) = *reinterpret_cast<const float4*>(gamma + base + 4);
    *reinterpret_cast<float4*>(&bt[0]) = *reinterpret_cast<const float4*>(beta + base);
    *reinterpret_cast<float4*>(&bt[4]) = *reinterpret_cast<const float4*>(beta + base + 4);

    float o8[8];
#pragma unroll
    for (int i = 0; i < 8; i++)
        o8[i] = (f[i] - mu) * rstd * gm[i] + bt[i];

    float* op = outA + (size_t)n * 256 + base;
    *reinterpret_cast<float4*>(op)     = *reinterpret_cast<float4*>(&o8[0]);
    *reinterpret_cast<float4*>(op + 4) = *reinterpret_cast<float4*>(&o8[4]);
}

// ---------------- launch ----------------------------------------------------
extern "C" void kernel_launch(void* const* d_in, const int* in_sizes, int n_in,
                              void* d_out, int out_size)
{
    const float* x_B  = (const float*)d_in[1];
    const int*   ei0  = (const int*)d_in[2];
    const int*   ei1  = (const int*)d_in[3];
    const float* W0   = (const float*)d_in[4];
    const float* b0   = (const float*)d_in[5];
    const float* W1   = (const float*)d_in[6];
    const float* b1   = (const float*)d_in[7];
    const float* sem  = (const float*)d_in[8];
    const float* gam  = (const float*)d_in[9];
    const float* bet  = (const float*)d_in[10];

    float* outA = (float*)d_out;
    float* outB = outA + (size_t)NA * OUT_DIM;

    cudaFuncSetAttribute(gemm_mma_kernel,
                         cudaFuncAttributeMaxDynamicSharedMemorySize, GSM_TOTAL);

    zero_hist_kernel<<<(NBIN / 4 + 255) / 256, 256>>>();
    splitW_kernel<<<512, 256>>>(W0, W1);

    hist_kernel<<<(2 * NE + 255) / 256, 256>>>(ei0, ei1);
    scanA_kernel<<<NBLK, SCAN_B>>>();
    scanB_kernel<<<1, SCAN_B>>>();
    scanC_kernel<<<NBLK, SCAN_B>>>();
    fill_kernel<<<(2 * NE + 255) / 256, 256>>>(ei0, ei1);

    agg_kernel<<<(NBIN * 32 + 255) / 256, 256>>>(x_B);

    {
        dim3 grid(4, (NA + 127) / 128);
        gemm_mma_kernel<<<grid, 256, GSM_TOTAL>>>(b0, b1);
    }

    finalize_kernel<<<FIN_BLOCKS + ZB_BLOCKS, 256>>>(sem, gam, bet, outA, outB);
}